// round 5
// baseline (speedup 1.0000x reference)
#include <cuda_runtime.h>

// out[b,d,t] = T*x[b,d,t] - 2 * sum_{s ≡ t (mod 2)} x[b,d,s],  T = 1024.
// Derivation: the reference's rfft -> drop DC/Nyquist -> cos/sin GEMM pipeline
// is linear in x; the combined kernel sum_{k=1}^{T/2-1} cos(2πk(s-t)/T) equals
// (T-2)/2 for s==t, -1 for s-t even nonzero, 0 for s-t odd.

#define ROW_LEN 1024
#define THREADS 256   // 4 floats per thread via float4

__global__ __launch_bounds__(THREADS)
void season_block_46428596469890_kernel(const float* __restrict__ x,
                                        float* __restrict__ out) {
    const long long row = blockIdx.x;
    const float4* __restrict__ xr =
        reinterpret_cast<const float4*>(x + row * ROW_LEN);
    float4* __restrict__ outr = reinterpret_cast<float4*>(out + row * ROW_LEN);

    const int tid  = threadIdx.x;
    const int lane = tid & 31;
    const int warp = tid >> 5;

    float4 v = xr[tid];

    // even indices are .x/.z of each float4 (t = 4*tid + {0,2}); odd are .y/.w
    float esum = v.x + v.z;
    float osum = v.y + v.w;

    // intra-warp reduction of the (even, odd) pair
    #pragma unroll
    for (int off = 16; off > 0; off >>= 1) {
        esum += __shfl_xor_sync(0xffffffffu, esum, off);
        osum += __shfl_xor_sync(0xffffffffu, osum, off);
    }

    __shared__ float se[8];
    __shared__ float so[8];
    if (lane == 0) { se[warp] = esum; so[warp] = osum; }
    __syncthreads();

    if (warp == 0) {
        float e = (lane < 8) ? se[lane] : 0.0f;
        float o = (lane < 8) ? so[lane] : 0.0f;
        #pragma unroll
        for (int off = 4; off > 0; off >>= 1) {
            e += __shfl_xor_sync(0xffffffffu, e, off);
            o += __shfl_xor_sync(0xffffffffu, o, off);
        }
        if (lane == 0) { se[0] = e; so[0] = o; }
    }
    __syncthreads();

    const float E2 = 2.0f * se[0];
    const float O2 = 2.0f * so[0];
    const float T  = (float)ROW_LEN;

    float4 r;
    r.x = fmaf(T, v.x, -E2);
    r.y = fmaf(T, v.y, -O2);
    r.z = fmaf(T, v.z, -E2);
    r.w = fmaf(T, v.w, -O2);
    outr[tid] = r;
}

extern "C" void kernel_launch(void* const* d_in, const int* in_sizes, int n_in,
                              void* d_out, int out_size) {
    const float* x = (const float*)d_in[0];
    float* out = (float*)d_out;
    const int n_rows = in_sizes[0] / ROW_LEN;   // 64*128 = 8192
    season_block_46428596469890_kernel<<<n_rows, THREADS>>>(x, out);
}

// round 6
// speedup vs baseline: 1.1901x; 1.1901x over previous
#include <cuda_runtime.h>

// out[b,d,t] = T*x[b,d,t] - 2 * sum_{s ≡ t (mod 2)} x[b,d,s],  T = 1024.
// (Dirichlet-kernel collapse of the rfft -> cos/sin GEMM reference; see R1.)
//
// R5: warp-per-row. Each warp holds a full 1024-float row in registers
// (8 x float4 per lane), reduces the (even,odd) pair with shuffles only —
// no shared memory, no __syncthreads — and stores from registers.

#define ROW_LEN   1024
#define THREADS   256            // 8 warps -> 8 rows per block
#define VEC_PER_LANE 8           // 8 float4 = 32 floats per lane

__global__ __launch_bounds__(THREADS)
void season_block_46428596469890_kernel(const float* __restrict__ x,
                                        float* __restrict__ out) {
    const int lane = threadIdx.x & 31;
    const int warp = threadIdx.x >> 5;
    const long long row = (long long)blockIdx.x * 8 + warp;

    const float4* __restrict__ xr =
        reinterpret_cast<const float4*>(x + row * ROW_LEN);
    float4* __restrict__ outr = reinterpret_cast<float4*>(out + row * ROW_LEN);

    // Front-batched independent loads: MLP = 8 per lane.
    float4 v[VEC_PER_LANE];
    #pragma unroll
    for (int j = 0; j < VEC_PER_LANE; j++)
        v[j] = xr[lane + 32 * j];

    // Element index of v[j].x is 4*(lane + 32j): .x/.z always even, .y/.w odd.
    float esum = 0.0f, osum = 0.0f;
    #pragma unroll
    for (int j = 0; j < VEC_PER_LANE; j++) {
        esum += v[j].x + v[j].z;
        osum += v[j].y + v[j].w;
    }

    // Warp-only reduction; every lane ends with the full row sums.
    #pragma unroll
    for (int off = 16; off > 0; off >>= 1) {
        esum += __shfl_xor_sync(0xffffffffu, esum, off);
        osum += __shfl_xor_sync(0xffffffffu, osum, off);
    }

    const float E2 = 2.0f * esum;
    const float O2 = 2.0f * osum;
    const float T  = (float)ROW_LEN;

    #pragma unroll
    for (int j = 0; j < VEC_PER_LANE; j++) {
        float4 r;
        r.x = fmaf(T, v[j].x, -E2);
        r.y = fmaf(T, v[j].y, -O2);
        r.z = fmaf(T, v[j].z, -E2);
        r.w = fmaf(T, v[j].w, -O2);
        outr[lane + 32 * j] = r;
    }
}

extern "C" void kernel_launch(void* const* d_in, const int* in_sizes, int n_in,
                              void* d_out, int out_size) {
    const float* x = (const float*)d_in[0];
    float* out = (float*)d_out;
    const int n_rows = in_sizes[0] / ROW_LEN;     // 8192
    season_block_46428596469890_kernel<<<n_rows / 8, THREADS>>>(x, out);
}